// round 11
// baseline (speedup 1.0000x reference)
#include <cuda_runtime.h>
#include <math.h>

#define N_SAMP 32
#define C_TOT 256
#define CPG 16
#define GROUPS 16
#define NG 512
#define HW 4096
#define NHW (N_SAMP * HW)
#define TRI 136
#define STATS_LEN 152          // 16 sums + 136 tri
#define EPS 1e-5f
#define T_ITERS 5

#define K1_SPLIT 2
#define K1_POS (HW / K1_SPLIT)   // 2048 positions per stats block
#define K3_SPLIT 4
#define K3_POS (HW / K3_SPLIT)   // 1024

// -------- scratch (device globals) --------
__device__ float g_part[NG][K1_SPLIT][STATS_LEN]; // per-(n,g,chunk) partial stats
__device__ float g_bw[GROUPS][STATS_LEN];         // per-group batch sums
__device__ float g_A[NG][CPG * CPG];
__device__ float g_b0[NG][CPG];

// ------------------------------------------------------------------
// Kernel 1: stats. grid = NG*K1_SPLIT blocks, 256 threads.
// Same proven 4-quarter-set float4 body as round 9; half the passes
// per block (wave-balance: 1024 short blocks instead of 512 long).
// ------------------------------------------------------------------
__global__ __launch_bounds__(256, 2) void stats_kernel(const float* __restrict__ x) {
    int b = blockIdx.x;
    int ng = b >> 1;
    int chunk = b & 1;
    int n = ng >> 4;
    int g = ng & 15;
    int tid = threadIdx.x;
    int q = tid >> 6;          // set 0..3
    int t = tid & 63;

    const float* __restrict__ xb =
        x + (size_t)(n * C_TOT + g * CPG) * HW + (size_t)chunk * K1_POS;

    float s[4];
    float acc[43];
#pragma unroll
    for (int i = 0; i < 4; i++) s[i] = 0.f;
#pragma unroll
    for (int i = 0; i < 43; i++) acc[i] = 0.f;

    // 64 threads/set x float4 = 256 positions per pass; K1_POS/256 = 8 passes.
    if (q == 0) {
#pragma unroll 1
        for (int pass = 0; pass < K1_POS / 256; pass++) {
            int p = pass * 256 + t * 4;
            float4 v[8];
#pragma unroll
            for (int c = 0; c < 8; c++)
                v[c] = *(const float4*)(xb + (size_t)c * HW + p);
#pragma unroll
            for (int c = 0; c < 4; c++) s[c] += (v[c].x + v[c].y) + (v[c].z + v[c].w);
            int idx = 0;
#pragma unroll
            for (int i = 0; i < 8; i++)
#pragma unroll
                for (int j = 0; j <= i; j++) {
                    acc[idx] += v[i].x * v[j].x + v[i].y * v[j].y
                              + v[i].z * v[j].z + v[i].w * v[j].w;
                    idx++;
                }
        }
    } else if (q == 1) {
#pragma unroll 1
        for (int pass = 0; pass < K1_POS / 256; pass++) {
            int p = pass * 256 + t * 4;
            float4 v[11];
#pragma unroll
            for (int c = 0; c < 11; c++)
                v[c] = *(const float4*)(xb + (size_t)c * HW + p);
#pragma unroll
            for (int c = 0; c < 4; c++) s[c] += (v[c + 4].x + v[c + 4].y) + (v[c + 4].z + v[c + 4].w);
            int idx = 0;
#pragma unroll
            for (int i = 8; i < 11; i++)
#pragma unroll
                for (int j = 0; j <= i; j++) {
                    acc[idx] += v[i].x * v[j].x + v[i].y * v[j].y
                              + v[i].z * v[j].z + v[i].w * v[j].w;
                    idx++;
                }
        }
    } else if (q == 2) {
#pragma unroll 1
        for (int pass = 0; pass < K1_POS / 256; pass++) {
            int p = pass * 256 + t * 4;
            float4 v[14];
#pragma unroll
            for (int c = 0; c < 14; c++)
                v[c] = *(const float4*)(xb + (size_t)c * HW + p);
#pragma unroll
            for (int c = 0; c < 4; c++) s[c] += (v[c + 8].x + v[c + 8].y) + (v[c + 8].z + v[c + 8].w);
            int idx = 0;
#pragma unroll
            for (int i = 11; i < 14; i++)
#pragma unroll
                for (int j = 0; j <= i; j++) {
                    acc[idx] += v[i].x * v[j].x + v[i].y * v[j].y
                              + v[i].z * v[j].z + v[i].w * v[j].w;
                    idx++;
                }
        }
    } else {
#pragma unroll 1
        for (int pass = 0; pass < K1_POS / 256; pass++) {
            int p = pass * 256 + t * 4;
            float4 v[16];
#pragma unroll
            for (int c = 0; c < 16; c++)
                v[c] = *(const float4*)(xb + (size_t)c * HW + p);
#pragma unroll
            for (int c = 0; c < 4; c++) s[c] += (v[c + 12].x + v[c + 12].y) + (v[c + 12].z + v[c + 12].w);
            int idx = 0;
#pragma unroll
            for (int i = 14; i < 16; i++)
#pragma unroll
                for (int j = 0; j <= i; j++) {
                    acc[idx] += v[i].x * v[j].x + v[i].y * v[j].y
                              + v[i].z * v[j].z + v[i].w * v[j].w;
                    idx++;
                }
        }
    }

    // warp butterfly reduce
#pragma unroll
    for (int k = 0; k < 4; k++) {
        float v = s[k];
        v += __shfl_xor_sync(0xffffffffu, v, 16);
        v += __shfl_xor_sync(0xffffffffu, v, 8);
        v += __shfl_xor_sync(0xffffffffu, v, 4);
        v += __shfl_xor_sync(0xffffffffu, v, 2);
        v += __shfl_xor_sync(0xffffffffu, v, 1);
        s[k] = v;
    }
#pragma unroll
    for (int k = 0; k < 43; k++) {
        float v = acc[k];
        v += __shfl_xor_sync(0xffffffffu, v, 16);
        v += __shfl_xor_sync(0xffffffffu, v, 8);
        v += __shfl_xor_sync(0xffffffffu, v, 4);
        v += __shfl_xor_sync(0xffffffffu, v, 2);
        v += __shfl_xor_sync(0xffffffffu, v, 1);
        acc[k] = v;
    }

    __shared__ float red[4][2][47];
    int warp = tid >> 5;
    int lane = tid & 31;
    int w2 = warp & 1;
    if (lane == 0) {
#pragma unroll
        for (int k = 0; k < 4; k++) red[q][w2][k] = s[k];
#pragma unroll
        for (int k = 0; k < 43; k++) red[q][w2][4 + k] = acc[k];
    }
    __syncthreads();

    // 152 outputs: set lengths 40 / 34 / 43 / 35
    if (tid < 152) {
        int set, loc;
        if (tid < 40)       { set = 0; loc = tid; }
        else if (tid < 74)  { set = 1; loc = tid - 40; }
        else if (tid < 117) { set = 2; loc = tid - 74; }
        else                { set = 3; loc = tid - 117; }
        float a = red[set][0][loc] + red[set][1][loc];
        int dst;
        if (loc < 4) dst = set * 4 + loc;                 // channel sums
        else {
            const int triBase[4] = {16, 52, 82, 121};     // 16 + {0,36,66,105}
            dst = triBase[set] + (loc - 4);
        }
        g_part[ng][chunk][dst] = a;
    }
}

// ------------------------------------------------------------------
// Kernel 1b: reduce batch-whitening sums per group ONCE. grid = GROUPS.
// ------------------------------------------------------------------
__global__ __launch_bounds__(256) void bw_kernel() {
    int g = blockIdx.x;
    int t = threadIdx.x;
    if (t < STATS_LEN) {
        float a = 0.f;
#pragma unroll 8
        for (int n = 0; n < N_SAMP; n++) {
            a += g_part[n * GROUPS + g][0][t];
            a += g_part[n * GROUPS + g][1][t];
        }
        g_bw[g][t] = a;
    }
}

// ------------------------------------------------------------------
// Kernel 2: mix stats, Newton-Schulz, fold affine.
// Iter 0 analytic (P=I). Double-buffered P: 3 syncs/iter for iters 1-4.
// ------------------------------------------------------------------
__global__ __launch_bounds__(256) void whiten_kernel(
    const float* __restrict__ sw_mean_w,
    const float* __restrict__ sw_var_w,
    const float* __restrict__ weight,
    const float* __restrict__ bias) {

    int ng = blockIdx.x;
    int g = ng & 15;
    int tid = threadIdx.x;
    int i = tid >> 4;
    int j = tid & 15;

    __shared__ float iw[STATS_LEN];
    __shared__ float bw[STATS_LEN];
    __shared__ float M[CPG][CPG + 1];       // covN (never overwritten)
    __shared__ float Pbuf[2][CPG][CPG + 1]; // ping-pong P
    __shared__ float T1[CPG][CPG + 1];
    __shared__ float T2[CPG][CPG + 1];
    __shared__ float meanmix[CPG];

    if (tid < STATS_LEN) {
        iw[tid] = g_part[ng][0][tid] + g_part[ng][1][tid];
        bw[tid] = g_bw[g][tid];
    }
    __syncthreads();

    int a_ = i > j ? i : j;
    int b_ = i > j ? j : i;
    int t = a_ * (a_ + 1) / 2 + b_;

    float sin_ij = iw[16 + t];
    float mi_i = iw[i] * (1.0f / HW);
    float mi_j = iw[j] * (1.0f / HW);
    float sbn = bw[16 + t];
    float mb_i = bw[i] * (1.0f / NHW);
    float mb_j = bw[j] * (1.0f / NHW);

    float cov_in = sin_ij * (1.0f / HW) - mi_i * mi_j;
    float cov_bn = sbn * (1.0f / NHW) - mb_i * mb_j;

    float w0 = sw_mean_w[0], w1 = sw_mean_w[1];
    float mm = fmaxf(w0, w1);
    float e0 = expf(w0 - mm), e1 = expf(w1 - mm);
    float mw0 = e0 / (e0 + e1);
    float mw1 = 1.0f - mw0;

    float v0 = sw_var_w[0], v1 = sw_var_w[1];
    float vm = fmaxf(v0, v1);
    float f0 = expf(v0 - vm), f1 = expf(v1 - vm);
    float vw0 = f0 / (f0 + f1);
    float vw1 = 1.0f - vw0;

    float cval = vw0 * cov_bn + vw1 * cov_in + (i == j ? EPS : 0.0f);
    M[i][j] = cval;                       // temporarily raw cov for trace
    if (i == 0) meanmix[j] = mw0 * mb_j + mw1 * mi_j;
    __syncthreads();

    float tr = 0.f;
#pragma unroll
    for (int k = 0; k < CPG; k++) tr += M[k][k];
    float rTr = 1.0f / tr;
    __syncthreads();   // finish trace reads before overwrite

    float covN_ij = cval * rTr;
    M[i][j] = covN_ij;
    // Iter 0 analytic: P1 = 1.5 I - 0.5 covN
    Pbuf[0][i][j] = (i == j ? 1.5f : 0.0f) - 0.5f * covN_ij;
    __syncthreads();

    int cur = 0;
    for (int iter = 1; iter < T_ITERS; iter++) {
        float acc = 0.f;
#pragma unroll
        for (int k = 0; k < CPG; k++) acc += Pbuf[cur][i][k] * Pbuf[cur][k][j];
        T1[i][j] = acc;
        __syncthreads();

        acc = 0.f;
#pragma unroll
        for (int k = 0; k < CPG; k++) acc += T1[i][k] * Pbuf[cur][k][j];
        T2[i][j] = acc;
        __syncthreads();

        acc = 0.f;
#pragma unroll
        for (int k = 0; k < CPG; k++) acc += T2[i][k] * M[k][j];
        Pbuf[1 - cur][i][j] = 1.5f * Pbuf[cur][i][j] - 0.5f * acc;
        __syncthreads();
        cur = 1 - cur;
    }

    float wm_ij = Pbuf[cur][i][j] * sqrtf(rTr);
    T1[i][j] = wm_ij;
    float A_ij = weight[g * CPG + i] * wm_ij;
    g_A[ng][i * CPG + j] = A_ij;
    __syncthreads();

    if (tid < CPG) {
        int c = tid;
        float wc = weight[g * CPG + c];
        float acc = 0.f;
#pragma unroll
        for (int d = 0; d < CPG; d++) acc += T1[c][d] * meanmix[d];
        g_b0[ng][c] = bias[g * CPG + c] - wc * acc;
    }
}

// ------------------------------------------------------------------
// Kernel 3: apply  out[c] = sum_d A[c][d]*x[d] + b0[c]   (float4)
// REVERSED block order: stats streamed x ascending, so the tail of x
// is L2-resident when apply starts — consume it first (LRU frontier).
// ------------------------------------------------------------------
__global__ __launch_bounds__(256) void apply_kernel(const float* __restrict__ x,
                                                    float* __restrict__ out) {
    int b = (NG * K3_SPLIT - 1) - blockIdx.x;   // reversed traversal
    int ng = b >> 2;                 // / K3_SPLIT
    int chunk = b & (K3_SPLIT - 1);
    int n = ng >> 4;
    int g = ng & 15;
    int tid = threadIdx.x;

    __shared__ float sA[CPG][CPG];
    __shared__ float sb[CPG];
    sA[tid >> 4][tid & 15] = g_A[ng][tid];
    if (tid < CPG) sb[tid] = g_b0[ng][tid];
    __syncthreads();

    size_t base = (size_t)(n * C_TOT + g * CPG) * HW
                + (size_t)chunk * K3_POS + (size_t)tid * 4;

    float4 v[CPG];
#pragma unroll
    for (int d = 0; d < CPG; d++)
        v[d] = *(const float4*)(x + base + (size_t)d * HW);

#pragma unroll
    for (int c = 0; c < CPG; c++) {
        float bc = sb[c];
        float4 acc = make_float4(bc, bc, bc, bc);
#pragma unroll
        for (int d = 0; d < CPG; d++) {
            float a = sA[c][d];
            acc.x += a * v[d].x;
            acc.y += a * v[d].y;
            acc.z += a * v[d].z;
            acc.w += a * v[d].w;
        }
        *(float4*)(out + base + (size_t)c * HW) = acc;
    }
}

// ------------------------------------------------------------------
extern "C" void kernel_launch(void* const* d_in, const int* in_sizes, int n_in,
                              void* d_out, int out_size) {
    const float* x      = (const float*)d_in[0];
    const float* sw_m   = (const float*)d_in[1];
    const float* sw_v   = (const float*)d_in[2];
    const float* weight = (const float*)d_in[3];
    const float* bias   = (const float*)d_in[4];
    float* out = (float*)d_out;

    stats_kernel<<<NG * K1_SPLIT, 256>>>(x);
    bw_kernel<<<GROUPS, 256>>>();
    whiten_kernel<<<NG, 256>>>(sw_m, sw_v, weight, bias);
    apply_kernel<<<NG * K3_SPLIT, 256>>>(x, out);
}

// round 12
// speedup vs baseline: 1.2142x; 1.2142x over previous
#include <cuda_runtime.h>
#include <math.h>

#define N_SAMP 32
#define C_TOT 256
#define CPG 16
#define GROUPS 16
#define NG 512
#define HW 4096
#define NHW (N_SAMP * HW)
#define STATS_LEN 152          // 16 sums + 136 cov entries (quadrant layout)
#define EPS 1e-5f
#define T_ITERS 5

#define K3_SPLIT 4
#define K3_POS (HW / K3_SPLIT)   // 1024

// g_part layout per (n,g):
//  [0:16)    channel sums (channel order)
//  [16:52)   Q00: tri rows 0-7   (i*(i+1)/2+j),        i,j in 0-7
//  [52:88)   Q11: tri rows 8-15 within cols 8-15 ((i-8)(i-7)/2+(j-8))
//  [88:120)  Q10a: rows 8-11  x cols 0-7  ((i-8)*8+j)
//  [120:152) Q10b: rows 12-15 x cols 0-7  ((i-12)*8+j)
__device__ float g_part[NG][STATS_LEN];
__device__ float g_bw[GROUPS][STATS_LEN];
__device__ float g_A[NG][CPG * CPG];
__device__ float g_b0[NG][CPG];

// ------------------------------------------------------------------
// Kernel 1: stats. grid = NG blocks, 256 threads, 4 sets of 64.
//  set0: ch0-7  float4, sums 0-3,  Q00 (36 accs)   16 passes
//  set1: ch8-15 float4, sums 8-11, Q11 (36 accs)   16 passes
//  set2: ch0-11 float2, sums 4-7,  Q10a (32 accs)  32 passes
//  set3: ch0-7+12-15 float2, sums 12-15, Q10b (32) 32 passes
// ------------------------------------------------------------------
__global__ __launch_bounds__(256, 3) void stats_kernel(const float* __restrict__ x) {
    int ng = blockIdx.x;
    int n = ng >> 4;
    int g = ng & 15;
    int tid = threadIdx.x;
    int q = tid >> 6;          // set 0..3
    int t = tid & 63;

    const float* __restrict__ xb = x + (size_t)(n * C_TOT + g * CPG) * HW;

    float s[4];
    float acc[36];
#pragma unroll
    for (int i = 0; i < 4; i++) s[i] = 0.f;
#pragma unroll
    for (int i = 0; i < 36; i++) acc[i] = 0.f;

    if (q == 0) {
#pragma unroll 1
        for (int pass = 0; pass < HW / 256; pass++) {
            int p = pass * 256 + t * 4;
            float4 v[8];
#pragma unroll
            for (int c = 0; c < 8; c++)
                v[c] = *(const float4*)(xb + (size_t)c * HW + p);
#pragma unroll
            for (int c = 0; c < 4; c++) s[c] += (v[c].x + v[c].y) + (v[c].z + v[c].w);
            int idx = 0;
#pragma unroll
            for (int i = 0; i < 8; i++)
#pragma unroll
                for (int j = 0; j <= i; j++) {
                    acc[idx] += v[i].x * v[j].x + v[i].y * v[j].y
                              + v[i].z * v[j].z + v[i].w * v[j].w;
                    idx++;
                }
        }
    } else if (q == 1) {
#pragma unroll 1
        for (int pass = 0; pass < HW / 256; pass++) {
            int p = pass * 256 + t * 4;
            float4 v[8];
#pragma unroll
            for (int c = 0; c < 8; c++)
                v[c] = *(const float4*)(xb + (size_t)(c + 8) * HW + p);
#pragma unroll
            for (int c = 0; c < 4; c++) s[c] += (v[c].x + v[c].y) + (v[c].z + v[c].w);
            int idx = 0;
#pragma unroll
            for (int i = 0; i < 8; i++)
#pragma unroll
                for (int j = 0; j <= i; j++) {
                    acc[idx] += v[i].x * v[j].x + v[i].y * v[j].y
                              + v[i].z * v[j].z + v[i].w * v[j].w;
                    idx++;
                }
        }
    } else if (q == 2) {
#pragma unroll 1
        for (int pass = 0; pass < HW / 128; pass++) {
            int p = pass * 128 + t * 2;
            float2 v[12];                 // 0-7: ch0-7, 8-11: ch8-11
#pragma unroll
            for (int c = 0; c < 12; c++)
                v[c] = *(const float2*)(xb + (size_t)c * HW + p);
#pragma unroll
            for (int c = 0; c < 4; c++) s[c] += v[c + 4].x + v[c + 4].y;
            int idx = 0;
#pragma unroll
            for (int r = 0; r < 4; r++)
#pragma unroll
                for (int c = 0; c < 8; c++) {
                    acc[idx] += v[8 + r].x * v[c].x + v[8 + r].y * v[c].y;
                    idx++;
                }
        }
    } else {
#pragma unroll 1
        for (int pass = 0; pass < HW / 128; pass++) {
            int p = pass * 128 + t * 2;
            float2 v[12];                 // 0-7: ch0-7, 8-11: ch12-15
#pragma unroll
            for (int c = 0; c < 8; c++)
                v[c] = *(const float2*)(xb + (size_t)c * HW + p);
#pragma unroll
            for (int c = 0; c < 4; c++)
                v[8 + c] = *(const float2*)(xb + (size_t)(c + 12) * HW + p);
#pragma unroll
            for (int c = 0; c < 4; c++) s[c] += v[8 + c].x + v[8 + c].y;
            int idx = 0;
#pragma unroll
            for (int r = 0; r < 4; r++)
#pragma unroll
                for (int c = 0; c < 8; c++) {
                    acc[idx] += v[8 + r].x * v[c].x + v[8 + r].y * v[c].y;
                    idx++;
                }
        }
    }

    // warp butterfly reduce
#pragma unroll
    for (int k = 0; k < 4; k++) {
        float v = s[k];
        v += __shfl_xor_sync(0xffffffffu, v, 16);
        v += __shfl_xor_sync(0xffffffffu, v, 8);
        v += __shfl_xor_sync(0xffffffffu, v, 4);
        v += __shfl_xor_sync(0xffffffffu, v, 2);
        v += __shfl_xor_sync(0xffffffffu, v, 1);
        s[k] = v;
    }
#pragma unroll
    for (int k = 0; k < 36; k++) {
        float v = acc[k];
        v += __shfl_xor_sync(0xffffffffu, v, 16);
        v += __shfl_xor_sync(0xffffffffu, v, 8);
        v += __shfl_xor_sync(0xffffffffu, v, 4);
        v += __shfl_xor_sync(0xffffffffu, v, 2);
        v += __shfl_xor_sync(0xffffffffu, v, 1);
        acc[k] = v;
    }

    __shared__ float red[4][2][40];
    int warp = tid >> 5;
    int lane = tid & 31;
    int w2 = warp & 1;
    if (lane == 0) {
#pragma unroll
        for (int k = 0; k < 4; k++) red[q][w2][k] = s[k];
#pragma unroll
        for (int k = 0; k < 36; k++) red[q][w2][4 + k] = acc[k];
    }
    __syncthreads();

    // 152 outputs: set lengths 40 / 40 / 36 / 36
    if (tid < 152) {
        int set, loc;
        if (tid < 40)       { set = 0; loc = tid; }
        else if (tid < 80)  { set = 1; loc = tid - 40; }
        else if (tid < 116) { set = 2; loc = tid - 80; }
        else                { set = 3; loc = tid - 116; }
        float a = red[set][0][loc] + red[set][1][loc];
        int dst;
        if (loc < 4) {
            const int sbase[4] = {0, 8, 4, 12};
            dst = sbase[set] + loc;
        } else {
            const int abase[4] = {16, 52, 88, 120};
            dst = abase[set] + (loc - 4);
        }
        g_part[ng][dst] = a;
    }
}

// ------------------------------------------------------------------
// Kernel 1b: reduce batch-whitening sums per group. grid = GROUPS.
// (layout-agnostic: element-wise sum over samples)
// ------------------------------------------------------------------
__global__ __launch_bounds__(256) void bw_kernel() {
    int g = blockIdx.x;
    int t = threadIdx.x;
    if (t < STATS_LEN) {
        float a = 0.f;
#pragma unroll 8
        for (int n = 0; n < N_SAMP; n++)
            a += g_part[n * GROUPS + g][t];
        g_bw[g][t] = a;
    }
}

// quadrant index for unordered pair (i>=j)
__device__ __forceinline__ int quad_idx(int i, int j) {
    if (i < 8)  return 16 + i * (i + 1) / 2 + j;
    if (j >= 8) { int a = i - 8, b = j - 8; return 52 + a * (a + 1) / 2 + b; }
    if (i < 12) return 88 + (i - 8) * 8 + j;
    return 120 + (i - 12) * 8 + j;
}

// ------------------------------------------------------------------
// Kernel 2: mix stats, Newton-Schulz, fold affine (round-10 version,
// only the stats index mapping changed).
// ------------------------------------------------------------------
__global__ __launch_bounds__(256) void whiten_kernel(
    const float* __restrict__ sw_mean_w,
    const float* __restrict__ sw_var_w,
    const float* __restrict__ weight,
    const float* __restrict__ bias) {

    int ng = blockIdx.x;
    int g = ng & 15;
    int tid = threadIdx.x;
    int i = tid >> 4;
    int j = tid & 15;

    __shared__ float iw[STATS_LEN];
    __shared__ float bw[STATS_LEN];
    __shared__ float M[CPG][CPG + 1];
    __shared__ float Pbuf[2][CPG][CPG + 1];
    __shared__ float T1[CPG][CPG + 1];
    __shared__ float T2[CPG][CPG + 1];
    __shared__ float meanmix[CPG];

    if (tid < STATS_LEN) {
        iw[tid] = g_part[ng][tid];
        bw[tid] = g_bw[g][tid];
    }
    __syncthreads();

    int i_ = i > j ? i : j;
    int j_ = i > j ? j : i;
    int t = quad_idx(i_, j_);

    float sin_ij = iw[t];
    float mi_i = iw[i] * (1.0f / HW);
    float mi_j = iw[j] * (1.0f / HW);
    float sbn = bw[t];
    float mb_i = bw[i] * (1.0f / NHW);
    float mb_j = bw[j] * (1.0f / NHW);

    float cov_in = sin_ij * (1.0f / HW) - mi_i * mi_j;
    float cov_bn = sbn * (1.0f / NHW) - mb_i * mb_j;

    float w0 = sw_mean_w[0], w1 = sw_mean_w[1];
    float mm = fmaxf(w0, w1);
    float e0 = expf(w0 - mm), e1 = expf(w1 - mm);
    float mw0 = e0 / (e0 + e1);
    float mw1 = 1.0f - mw0;

    float v0 = sw_var_w[0], v1 = sw_var_w[1];
    float vm = fmaxf(v0, v1);
    float f0 = expf(v0 - vm), f1 = expf(v1 - vm);
    float vw0 = f0 / (f0 + f1);
    float vw1 = 1.0f - vw0;

    float cval = vw0 * cov_bn + vw1 * cov_in + (i == j ? EPS : 0.0f);
    M[i][j] = cval;
    if (i == 0) meanmix[j] = mw0 * mb_j + mw1 * mi_j;
    __syncthreads();

    float tr = 0.f;
#pragma unroll
    for (int k = 0; k < CPG; k++) tr += M[k][k];
    float rTr = 1.0f / tr;
    __syncthreads();

    float covN_ij = cval * rTr;
    M[i][j] = covN_ij;
    Pbuf[0][i][j] = (i == j ? 1.5f : 0.0f) - 0.5f * covN_ij;
    __syncthreads();

    int cur = 0;
    for (int iter = 1; iter < T_ITERS; iter++) {
        float acc = 0.f;
#pragma unroll
        for (int k = 0; k < CPG; k++) acc += Pbuf[cur][i][k] * Pbuf[cur][k][j];
        T1[i][j] = acc;
        __syncthreads();

        acc = 0.f;
#pragma unroll
        for (int k = 0; k < CPG; k++) acc += T1[i][k] * Pbuf[cur][k][j];
        T2[i][j] = acc;
        __syncthreads();

        acc = 0.f;
#pragma unroll
        for (int k = 0; k < CPG; k++) acc += T2[i][k] * M[k][j];
        Pbuf[1 - cur][i][j] = 1.5f * Pbuf[cur][i][j] - 0.5f * acc;
        __syncthreads();
        cur = 1 - cur;
    }

    float wm_ij = Pbuf[cur][i][j] * sqrtf(rTr);
    T1[i][j] = wm_ij;
    float A_ij = weight[g * CPG + i] * wm_ij;
    g_A[ng][i * CPG + j] = A_ij;
    __syncthreads();

    if (tid < CPG) {
        int c = tid;
        float wc = weight[g * CPG + c];
        float acc = 0.f;
#pragma unroll
        for (int d = 0; d < CPG; d++) acc += T1[c][d] * meanmix[d];
        g_b0[ng][c] = bias[g * CPG + c] - wc * acc;
    }
}

// ------------------------------------------------------------------
// Kernel 3: apply (round-10 forward order — 39.0us, 69% DRAM).
// ------------------------------------------------------------------
__global__ __launch_bounds__(256) void apply_kernel(const float* __restrict__ x,
                                                    float* __restrict__ out) {
    int b = blockIdx.x;
    int ng = b >> 2;                 // / K3_SPLIT
    int chunk = b & (K3_SPLIT - 1);
    int n = ng >> 4;
    int g = ng & 15;
    int tid = threadIdx.x;

    __shared__ float sA[CPG][CPG];
    __shared__ float sb[CPG];
    sA[tid >> 4][tid & 15] = g_A[ng][tid];
    if (tid < CPG) sb[tid] = g_b0[ng][tid];
    __syncthreads();

    size_t base = (size_t)(n * C_TOT + g * CPG) * HW
                + (size_t)chunk * K3_POS + (size_t)tid * 4;

    float4 v[CPG];
#pragma unroll
    for (int d = 0; d < CPG; d++)
        v[d] = *(const float4*)(x + base + (size_t)d * HW);

#pragma unroll
    for (int c = 0; c < CPG; c++) {
        float bc = sb[c];
        float4 acc = make_float4(bc, bc, bc, bc);
#pragma unroll
        for (int d = 0; d < CPG; d++) {
            float a = sA[c][d];
            acc.x += a * v[d].x;
            acc.y += a * v[d].y;
            acc.z += a * v[d].z;
            acc.w += a * v[d].w;
        }
        *(float4*)(out + base + (size_t)c * HW) = acc;
    }
}

// ------------------------------------------------------------------
extern "C" void kernel_launch(void* const* d_in, const int* in_sizes, int n_in,
                              void* d_out, int out_size) {
    const float* x      = (const float*)d_in[0];
    const float* sw_m   = (const float*)d_in[1];
    const float* sw_v   = (const float*)d_in[2];
    const float* weight = (const float*)d_in[3];
    const float* bias   = (const float*)d_in[4];
    float* out = (float*)d_out;

    stats_kernel<<<NG, 256>>>(x);
    bw_kernel<<<GROUPS, 256>>>();
    whiten_kernel<<<NG, 256>>>(sw_m, sw_v, weight, bias);
    apply_kernel<<<NG * K3_SPLIT, 256>>>(x, out);
}

// round 13
// speedup vs baseline: 1.3163x; 1.0841x over previous
#include <cuda_runtime.h>
#include <math.h>

#define N_SAMP 32
#define C_TOT 256
#define CPG 16
#define GROUPS 16
#define NG 512
#define HW 4096
#define NHW (N_SAMP * HW)
#define STATS_LEN 152          // 16 sums + 136 tri (row-major triangle)
#define EPS 1e-5f
#define T_ITERS 5

#define K3_SPLIT 4
#define K3_POS (HW / K3_SPLIT)   // 1024

#define TILE_POS 256             // positions per smem tile
#define N_TILES (HW / TILE_POS)  // 16

// -------- scratch (device globals) --------
__device__ float g_part[NG][STATS_LEN];   // [0:16)=sums, [16:152)=tri row-major
__device__ float g_bw[GROUPS][STATS_LEN];
__device__ float g_A[NG][CPG * CPG];
__device__ float g_b0[NG][CPG];

// ------------------------------------------------------------------
// Kernel 1: stats, smem double-buffered pipeline.
// grid = NG blocks, 256 threads, 4 quarter-sets of 64 threads:
//   set 0: sums 0-3   + tri rows 0-7   (36 accs, reads ch 0-7)
//   set 1: sums 4-7   + tri rows 8-10  (30 accs, reads ch 0-10)
//   set 2: sums 8-11  + tri rows 11-13 (39 accs, reads ch 0-13)
//   set 3: sums 12-15 + tri rows 14-15 (31 accs, reads ch 0-15)
// Tile = 16 ch x 256 pos fp32 (16 KB), 2 buffers. LDGs for tile k+1
// issue before computing tile k -> DRAM latency hidden by compute.
// ------------------------------------------------------------------
__global__ __launch_bounds__(256, 2) void stats_kernel(const float* __restrict__ x) {
    int ng = blockIdx.x;
    int n = ng >> 4;
    int g = ng & 15;
    int tid = threadIdx.x;
    int q = tid >> 6;          // set 0..3
    int t = tid & 63;          // float4 slot within tile (position t*4..t*4+3)

    const float4* __restrict__ xb4 =
        (const float4*)(x + (size_t)(n * C_TOT + g * CPG) * HW);  // 1024 float4/ch

    __shared__ float4 tile[2][CPG * 64];   // [buf][ch*64 + slot], 16 KB each

    float s[4];
    float acc[43];
#pragma unroll
    for (int i = 0; i < 4; i++) s[i] = 0.f;
#pragma unroll
    for (int i = 0; i < 43; i++) acc[i] = 0.f;

    // loader mapping: i-th load -> slot sidx = i*256+tid; ch = sidx>>6; p4 = sidx&63
    float4 ld[4];
#pragma unroll
    for (int i = 0; i < 4; i++) {
        int sidx = i * 256 + tid;
        ld[i] = xb4[(sidx >> 6) * 1024 + (sidx & 63)];          // tile 0
    }
#pragma unroll
    for (int i = 0; i < 4; i++) tile[0][i * 256 + tid] = ld[i];
    __syncthreads();

#pragma unroll 1
    for (int k = 0; k < N_TILES; k++) {
        int cur = k & 1;
        if (k < N_TILES - 1) {
#pragma unroll
            for (int i = 0; i < 4; i++) {
                int sidx = i * 256 + tid;
                ld[i] = xb4[(sidx >> 6) * 1024 + (k + 1) * 64 + (sidx & 63)];
            }
        }

        const float4* tc = tile[cur];
        if (q == 0) {
            float4 v[8];
#pragma unroll
            for (int c = 0; c < 8; c++) v[c] = tc[c * 64 + t];
#pragma unroll
            for (int c = 0; c < 4; c++) s[c] += (v[c].x + v[c].y) + (v[c].z + v[c].w);
            int idx = 0;
#pragma unroll
            for (int i = 0; i < 8; i++)
#pragma unroll
                for (int j = 0; j <= i; j++) {
                    acc[idx] += v[i].x * v[j].x + v[i].y * v[j].y
                              + v[i].z * v[j].z + v[i].w * v[j].w;
                    idx++;
                }
        } else if (q == 1) {
            float4 v[11];
#pragma unroll
            for (int c = 0; c < 11; c++) v[c] = tc[c * 64 + t];
#pragma unroll
            for (int c = 0; c < 4; c++) s[c] += (v[c + 4].x + v[c + 4].y) + (v[c + 4].z + v[c + 4].w);
            int idx = 0;
#pragma unroll
            for (int i = 8; i < 11; i++)
#pragma unroll
                for (int j = 0; j <= i; j++) {
                    acc[idx] += v[i].x * v[j].x + v[i].y * v[j].y
                              + v[i].z * v[j].z + v[i].w * v[j].w;
                    idx++;
                }
        } else if (q == 2) {
            float4 v[14];
#pragma unroll
            for (int c = 0; c < 14; c++) v[c] = tc[c * 64 + t];
#pragma unroll
            for (int c = 0; c < 4; c++) s[c] += (v[c + 8].x + v[c + 8].y) + (v[c + 8].z + v[c + 8].w);
            int idx = 0;
#pragma unroll
            for (int i = 11; i < 14; i++)
#pragma unroll
                for (int j = 0; j <= i; j++) {
                    acc[idx] += v[i].x * v[j].x + v[i].y * v[j].y
                              + v[i].z * v[j].z + v[i].w * v[j].w;
                    idx++;
                }
        } else {
            float4 v[16];
#pragma unroll
            for (int c = 0; c < 16; c++) v[c] = tc[c * 64 + t];
#pragma unroll
            for (int c = 0; c < 4; c++) s[c] += (v[c + 12].x + v[c + 12].y) + (v[c + 12].z + v[c + 12].w);
            int idx = 0;
#pragma unroll
            for (int i = 14; i < 16; i++)
#pragma unroll
                for (int j = 0; j <= i; j++) {
                    acc[idx] += v[i].x * v[j].x + v[i].y * v[j].y
                              + v[i].z * v[j].z + v[i].w * v[j].w;
                    idx++;
                }
        }
        __syncthreads();                  // all reads of tile[cur] done
        if (k < N_TILES - 1) {
#pragma unroll
            for (int i = 0; i < 4; i++) tile[1 - cur][i * 256 + tid] = ld[i];
        }
        __syncthreads();                  // next buffer filled
    }

    // warp butterfly reduce (proven tail, unchanged)
#pragma unroll
    for (int k = 0; k < 4; k++) {
        float v = s[k];
        v += __shfl_xor_sync(0xffffffffu, v, 16);
        v += __shfl_xor_sync(0xffffffffu, v, 8);
        v += __shfl_xor_sync(0xffffffffu, v, 4);
        v += __shfl_xor_sync(0xffffffffu, v, 2);
        v += __shfl_xor_sync(0xffffffffu, v, 1);
        s[k] = v;
    }
#pragma unroll
    for (int k = 0; k < 43; k++) {
        float v = acc[k];
        v += __shfl_xor_sync(0xffffffffu, v, 16);
        v += __shfl_xor_sync(0xffffffffu, v, 8);
        v += __shfl_xor_sync(0xffffffffu, v, 4);
        v += __shfl_xor_sync(0xffffffffu, v, 2);
        v += __shfl_xor_sync(0xffffffffu, v, 1);
        acc[k] = v;
    }

    __shared__ float red[4][2][47];
    int warp = tid >> 5;
    int lane = tid & 31;
    int w2 = warp & 1;
    if (lane == 0) {
#pragma unroll
        for (int k = 0; k < 4; k++) red[q][w2][k] = s[k];
#pragma unroll
        for (int k = 0; k < 43; k++) red[q][w2][4 + k] = acc[k];
    }
    __syncthreads();

    // 152 outputs: set lengths 40 / 34 / 43 / 35 (round-9 mapping, proven)
    if (tid < 152) {
        int set, loc;
        if (tid < 40)       { set = 0; loc = tid; }
        else if (tid < 74)  { set = 1; loc = tid - 40; }
        else if (tid < 117) { set = 2; loc = tid - 74; }
        else                { set = 3; loc = tid - 117; }
        float a = red[set][0][loc] + red[set][1][loc];
        int dst;
        if (loc < 4) dst = set * 4 + loc;                 // channel sums
        else {
            const int triBase[4] = {16, 52, 82, 121};     // 16 + {0,36,66,105}
            dst = triBase[set] + (loc - 4);
        }
        g_part[ng][dst] = a;
    }
}

// ------------------------------------------------------------------
// Kernel 1b: reduce batch-whitening sums per group ONCE. grid = GROUPS.
// ------------------------------------------------------------------
__global__ __launch_bounds__(256) void bw_kernel() {
    int g = blockIdx.x;
    int t = threadIdx.x;
    if (t < STATS_LEN) {
        float a = 0.f;
#pragma unroll 8
        for (int n = 0; n < N_SAMP; n++)
            a += g_part[n * GROUPS + g][t];
        g_bw[g][t] = a;
    }
}

// ------------------------------------------------------------------
// Kernel 2: mix stats, Newton-Schulz, fold affine (round-10 exact).
// ------------------------------------------------------------------
__global__ __launch_bounds__(256) void whiten_kernel(
    const float* __restrict__ sw_mean_w,
    const float* __restrict__ sw_var_w,
    const float* __restrict__ weight,
    const float* __restrict__ bias) {

    int ng = blockIdx.x;
    int g = ng & 15;
    int tid = threadIdx.x;
    int i = tid >> 4;
    int j = tid & 15;

    __shared__ float iw[STATS_LEN];
    __shared__ float bw[STATS_LEN];
    __shared__ float M[CPG][CPG + 1];
    __shared__ float Pbuf[2][CPG][CPG + 1];
    __shared__ float T1[CPG][CPG + 1];
    __shared__ float T2[CPG][CPG + 1];
    __shared__ float meanmix[CPG];

    if (tid < STATS_LEN) {
        iw[tid] = g_part[ng][tid];
        bw[tid] = g_bw[g][tid];
    }
    __syncthreads();

    int a_ = i > j ? i : j;
    int b_ = i > j ? j : i;
    int t = a_ * (a_ + 1) / 2 + b_;

    float sin_ij = iw[16 + t];
    float mi_i = iw[i] * (1.0f / HW);
    float mi_j = iw[j] * (1.0f / HW);
    float sbn = bw[16 + t];
    float mb_i = bw[i] * (1.0f / NHW);
    float mb_j = bw[j] * (1.0f / NHW);

    float cov_in = sin_ij * (1.0f / HW) - mi_i * mi_j;
    float cov_bn = sbn * (1.0f / NHW) - mb_i * mb_j;

    float w0 = sw_mean_w[0], w1 = sw_mean_w[1];
    float mm = fmaxf(w0, w1);
    float e0 = expf(w0 - mm), e1 = expf(w1 - mm);
    float mw0 = e0 / (e0 + e1);
    float mw1 = 1.0f - mw0;

    float v0 = sw_var_w[0], v1 = sw_var_w[1];
    float vm = fmaxf(v0, v1);
    float f0 = expf(v0 - vm), f1 = expf(v1 - vm);
    float vw0 = f0 / (f0 + f1);
    float vw1 = 1.0f - vw0;

    float cval = vw0 * cov_bn + vw1 * cov_in + (i == j ? EPS : 0.0f);
    M[i][j] = cval;
    if (i == 0) meanmix[j] = mw0 * mb_j + mw1 * mi_j;
    __syncthreads();

    float tr = 0.f;
#pragma unroll
    for (int k = 0; k < CPG; k++) tr += M[k][k];
    float rTr = 1.0f / tr;
    __syncthreads();

    float covN_ij = cval * rTr;
    M[i][j] = covN_ij;
    Pbuf[0][i][j] = (i == j ? 1.5f : 0.0f) - 0.5f * covN_ij;
    __syncthreads();

    int cur = 0;
    for (int iter = 1; iter < T_ITERS; iter++) {
        float acc = 0.f;
#pragma unroll
        for (int k = 0; k < CPG; k++) acc += Pbuf[cur][i][k] * Pbuf[cur][k][j];
        T1[i][j] = acc;
        __syncthreads();

        acc = 0.f;
#pragma unroll
        for (int k = 0; k < CPG; k++) acc += T1[i][k] * Pbuf[cur][k][j];
        T2[i][j] = acc;
        __syncthreads();

        acc = 0.f;
#pragma unroll
        for (int k = 0; k < CPG; k++) acc += T2[i][k] * M[k][j];
        Pbuf[1 - cur][i][j] = 1.5f * Pbuf[cur][i][j] - 0.5f * acc;
        __syncthreads();
        cur = 1 - cur;
    }

    float wm_ij = Pbuf[cur][i][j] * sqrtf(rTr);
    T1[i][j] = wm_ij;
    float A_ij = weight[g * CPG + i] * wm_ij;
    g_A[ng][i * CPG + j] = A_ij;
    __syncthreads();

    if (tid < CPG) {
        int c = tid;
        float wc = weight[g * CPG + c];
        float acc = 0.f;
#pragma unroll
        for (int d = 0; d < CPG; d++) acc += T1[c][d] * meanmix[d];
        g_b0[ng][c] = bias[g * CPG + c] - wc * acc;
    }
}

// ------------------------------------------------------------------
// Kernel 3: apply (round-10 exact: forward order, float4, 69% DRAM).
// ------------------------------------------------------------------
__global__ __launch_bounds__(256) void apply_kernel(const float* __restrict__ x,
                                                    float* __restrict__ out) {
    int b = blockIdx.x;
    int ng = b >> 2;                 // / K3_SPLIT
    int chunk = b & (K3_SPLIT - 1);
    int n = ng >> 4;
    int g = ng & 15;
    int tid = threadIdx.x;

    __shared__ float sA[CPG][CPG];
    __shared__ float sb[CPG];
    sA[tid >> 4][tid & 15] = g_A[ng][tid];
    if (tid < CPG) sb[tid] = g_b0[ng][tid];
    __syncthreads();

    size_t base = (size_t)(n * C_TOT + g * CPG) * HW
                + (size_t)chunk * K3_POS + (size_t)tid * 4;

    float4 v[CPG];
#pragma unroll
    for (int d = 0; d < CPG; d++)
        v[d] = *(const float4*)(x + base + (size_t)d * HW);

#pragma unroll
    for (int c = 0; c < CPG; c++) {
        float bc = sb[c];
        float4 acc = make_float4(bc, bc, bc, bc);
#pragma unroll
        for (int d = 0; d < CPG; d++) {
            float a = sA[c][d];
            acc.x += a * v[d].x;
            acc.y += a * v[d].y;
            acc.z += a * v[d].z;
            acc.w += a * v[d].w;
        }
        *(float4*)(out + base + (size_t)c * HW) = acc;
    }
}

// ------------------------------------------------------------------
extern "C" void kernel_launch(void* const* d_in, const int* in_sizes, int n_in,
                              void* d_out, int out_size) {
    const float* x      = (const float*)d_in[0];
    const float* sw_m   = (const float*)d_in[1];
    const float* sw_v   = (const float*)d_in[2];
    const float* weight = (const float*)d_in[3];
    const float* bias   = (const float*)d_in[4];
    float* out = (float*)d_out;

    stats_kernel<<<NG, 256>>>(x);
    bw_kernel<<<GROUPS, 256>>>();
    whiten_kernel<<<NG, 256>>>(sw_m, sw_v, weight, bias);
    apply_kernel<<<NG * K3_SPLIT, 256>>>(x, out);
}

// round 14
// speedup vs baseline: 1.3687x; 1.0398x over previous
#include <cuda_runtime.h>
#include <math.h>

#define N_SAMP 32
#define C_TOT 256
#define CPG 16
#define GROUPS 16
#define NG 512
#define HW 4096
#define NHW (N_SAMP * HW)
#define STATS_LEN 152          // 16 sums + 136 tri row-major
#define EPS 1e-5f
#define T_ITERS 5

#define K3_SPLIT 4
#define K3_POS (HW / K3_SPLIT)   // 1024

// -------- scratch (device globals) --------
__device__ float g_part[NG][STATS_LEN];
__device__ float g_bw[GROUPS][STATS_LEN];
__device__ float g_A[NG][CPG * CPG];
__device__ float g_b0[NG][CPG];

// ------------------------------------------------------------------
// Kernel 1: stats (round-9 exact — 38.4us proven).
// ------------------------------------------------------------------
__global__ __launch_bounds__(256, 2) void stats_kernel(const float* __restrict__ x) {
    int ng = blockIdx.x;
    int n = ng >> 4;
    int g = ng & 15;
    int tid = threadIdx.x;
    int q = tid >> 6;          // set 0..3
    int t = tid & 63;

    const float* __restrict__ xb = x + (size_t)(n * C_TOT + g * CPG) * HW;

    float s[4];
    float acc[43];
#pragma unroll
    for (int i = 0; i < 4; i++) s[i] = 0.f;
#pragma unroll
    for (int i = 0; i < 43; i++) acc[i] = 0.f;

    if (q == 0) {
#pragma unroll 1
        for (int pass = 0; pass < HW / 256; pass++) {
            int p = pass * 256 + t * 4;
            float4 v[8];
#pragma unroll
            for (int c = 0; c < 8; c++)
                v[c] = *(const float4*)(xb + (size_t)c * HW + p);
#pragma unroll
            for (int c = 0; c < 4; c++) s[c] += (v[c].x + v[c].y) + (v[c].z + v[c].w);
            int idx = 0;
#pragma unroll
            for (int i = 0; i < 8; i++)
#pragma unroll
                for (int j = 0; j <= i; j++) {
                    acc[idx] += v[i].x * v[j].x + v[i].y * v[j].y
                              + v[i].z * v[j].z + v[i].w * v[j].w;
                    idx++;
                }
        }
    } else if (q == 1) {
#pragma unroll 1
        for (int pass = 0; pass < HW / 256; pass++) {
            int p = pass * 256 + t * 4;
            float4 v[11];
#pragma unroll
            for (int c = 0; c < 11; c++)
                v[c] = *(const float4*)(xb + (size_t)c * HW + p);
#pragma unroll
            for (int c = 0; c < 4; c++) s[c] += (v[c + 4].x + v[c + 4].y) + (v[c + 4].z + v[c + 4].w);
            int idx = 0;
#pragma unroll
            for (int i = 8; i < 11; i++)
#pragma unroll
                for (int j = 0; j <= i; j++) {
                    acc[idx] += v[i].x * v[j].x + v[i].y * v[j].y
                              + v[i].z * v[j].z + v[i].w * v[j].w;
                    idx++;
                }
        }
    } else if (q == 2) {
#pragma unroll 1
        for (int pass = 0; pass < HW / 256; pass++) {
            int p = pass * 256 + t * 4;
            float4 v[14];
#pragma unroll
            for (int c = 0; c < 14; c++)
                v[c] = *(const float4*)(xb + (size_t)c * HW + p);
#pragma unroll
            for (int c = 0; c < 4; c++) s[c] += (v[c + 8].x + v[c + 8].y) + (v[c + 8].z + v[c + 8].w);
            int idx = 0;
#pragma unroll
            for (int i = 11; i < 14; i++)
#pragma unroll
                for (int j = 0; j <= i; j++) {
                    acc[idx] += v[i].x * v[j].x + v[i].y * v[j].y
                              + v[i].z * v[j].z + v[i].w * v[j].w;
                    idx++;
                }
        }
    } else {
#pragma unroll 1
        for (int pass = 0; pass < HW / 256; pass++) {
            int p = pass * 256 + t * 4;
            float4 v[16];
#pragma unroll
            for (int c = 0; c < 16; c++)
                v[c] = *(const float4*)(xb + (size_t)c * HW + p);
#pragma unroll
            for (int c = 0; c < 4; c++) s[c] += (v[c + 12].x + v[c + 12].y) + (v[c + 12].z + v[c + 12].w);
            int idx = 0;
#pragma unroll
            for (int i = 14; i < 16; i++)
#pragma unroll
                for (int j = 0; j <= i; j++) {
                    acc[idx] += v[i].x * v[j].x + v[i].y * v[j].y
                              + v[i].z * v[j].z + v[i].w * v[j].w;
                    idx++;
                }
        }
    }

#pragma unroll
    for (int k = 0; k < 4; k++) {
        float v = s[k];
        v += __shfl_xor_sync(0xffffffffu, v, 16);
        v += __shfl_xor_sync(0xffffffffu, v, 8);
        v += __shfl_xor_sync(0xffffffffu, v, 4);
        v += __shfl_xor_sync(0xffffffffu, v, 2);
        v += __shfl_xor_sync(0xffffffffu, v, 1);
        s[k] = v;
    }
#pragma unroll
    for (int k = 0; k < 43; k++) {
        float v = acc[k];
        v += __shfl_xor_sync(0xffffffffu, v, 16);
        v += __shfl_xor_sync(0xffffffffu, v, 8);
        v += __shfl_xor_sync(0xffffffffu, v, 4);
        v += __shfl_xor_sync(0xffffffffu, v, 2);
        v += __shfl_xor_sync(0xffffffffu, v, 1);
        acc[k] = v;
    }

    __shared__ float red[4][2][47];
    int warp = tid >> 5;
    int lane = tid & 31;
    int w2 = warp & 1;
    if (lane == 0) {
#pragma unroll
        for (int k = 0; k < 4; k++) red[q][w2][k] = s[k];
#pragma unroll
        for (int k = 0; k < 43; k++) red[q][w2][4 + k] = acc[k];
    }
    __syncthreads();

    if (tid < 152) {
        int set, loc;
        if (tid < 40)       { set = 0; loc = tid; }
        else if (tid < 74)  { set = 1; loc = tid - 40; }
        else if (tid < 117) { set = 2; loc = tid - 74; }
        else                { set = 3; loc = tid - 117; }
        float a = red[set][0][loc] + red[set][1][loc];
        int dst;
        if (loc < 4) dst = set * 4 + loc;
        else {
            const int triBase[4] = {16, 52, 82, 121};
            dst = triBase[set] + (loc - 4);
        }
        g_part[ng][dst] = a;
    }
}

// ------------------------------------------------------------------
// Kernel 1b: BW reduction. Triggers early PDL release of whiten.
// ------------------------------------------------------------------
__global__ __launch_bounds__(256) void bw_kernel() {
    int g = blockIdx.x;
    int t = threadIdx.x;
    if (t < STATS_LEN) {
        float a = 0.f;
#pragma unroll 8
        for (int n = 0; n < N_SAMP; n++)
            a += g_part[n * GROUPS + g][t];
        g_bw[g][t] = a;
    }
    cudaTriggerProgrammaticLaunchCompletion();
}

// ------------------------------------------------------------------
// Kernel 2: whiten (round-10 math). PDL: prefetch IW stats (stats
// output, already complete) before waiting on bw.
// ------------------------------------------------------------------
__global__ __launch_bounds__(256) void whiten_kernel(
    const float* __restrict__ sw_mean_w,
    const float* __restrict__ sw_var_w,
    const float* __restrict__ weight,
    const float* __restrict__ bias) {

    int ng = blockIdx.x;
    int g = ng & 15;
    int tid = threadIdx.x;
    int i = tid >> 4;
    int j = tid & 15;

    __shared__ float iw[STATS_LEN];
    __shared__ float bw[STATS_LEN];
    __shared__ float M[CPG][CPG + 1];
    __shared__ float Pbuf[2][CPG][CPG + 1];
    __shared__ float T1[CPG][CPG + 1];
    __shared__ float T2[CPG][CPG + 1];
    __shared__ float meanmix[CPG];

    // prework: IW stats depend only on stats_kernel (already finished)
    float iw_pre = 0.f;
    if (tid < STATS_LEN) iw_pre = g_part[ng][tid];

    cudaGridDependencySynchronize();      // wait for bw_kernel grid

    if (tid < STATS_LEN) {
        iw[tid] = iw_pre;
        bw[tid] = g_bw[g][tid];
    }
    __syncthreads();

    int a_ = i > j ? i : j;
    int b_ = i > j ? j : i;
    int t = a_ * (a_ + 1) / 2 + b_;

    float sin_ij = iw[16 + t];
    float mi_i = iw[i] * (1.0f / HW);
    float mi_j = iw[j] * (1.0f / HW);
    float sbn = bw[16 + t];
    float mb_i = bw[i] * (1.0f / NHW);
    float mb_j = bw[j] * (1.0f / NHW);

    float cov_in = sin_ij * (1.0f / HW) - mi_i * mi_j;
    float cov_bn = sbn * (1.0f / NHW) - mb_i * mb_j;

    float w0 = sw_mean_w[0], w1 = sw_mean_w[1];
    float mm = fmaxf(w0, w1);
    float e0 = expf(w0 - mm), e1 = expf(w1 - mm);
    float mw0 = e0 / (e0 + e1);
    float mw1 = 1.0f - mw0;

    float v0 = sw_var_w[0], v1 = sw_var_w[1];
    float vm = fmaxf(v0, v1);
    float f0 = expf(v0 - vm), f1 = expf(v1 - vm);
    float vw0 = f0 / (f0 + f1);
    float vw1 = 1.0f - vw0;

    float cval = vw0 * cov_bn + vw1 * cov_in + (i == j ? EPS : 0.0f);
    M[i][j] = cval;
    if (i == 0) meanmix[j] = mw0 * mb_j + mw1 * mi_j;
    __syncthreads();

    float tr = 0.f;
#pragma unroll
    for (int k = 0; k < CPG; k++) tr += M[k][k];
    float rTr = 1.0f / tr;
    __syncthreads();

    float covN_ij = cval * rTr;
    M[i][j] = covN_ij;
    Pbuf[0][i][j] = (i == j ? 1.5f : 0.0f) - 0.5f * covN_ij;
    __syncthreads();

    int cur = 0;
    for (int iter = 1; iter < T_ITERS; iter++) {
        float acc = 0.f;
#pragma unroll
        for (int k = 0; k < CPG; k++) acc += Pbuf[cur][i][k] * Pbuf[cur][k][j];
        T1[i][j] = acc;
        __syncthreads();

        acc = 0.f;
#pragma unroll
        for (int k = 0; k < CPG; k++) acc += T1[i][k] * Pbuf[cur][k][j];
        T2[i][j] = acc;
        __syncthreads();

        acc = 0.f;
#pragma unroll
        for (int k = 0; k < CPG; k++) acc += T2[i][k] * M[k][j];
        Pbuf[1 - cur][i][j] = 1.5f * Pbuf[cur][i][j] - 0.5f * acc;
        __syncthreads();
        cur = 1 - cur;
    }

    float wm_ij = Pbuf[cur][i][j] * sqrtf(rTr);
    T1[i][j] = wm_ij;
    float A_ij = weight[g * CPG + i] * wm_ij;
    g_A[ng][i * CPG + j] = A_ij;
    __syncthreads();

    if (tid < CPG) {
        int c = tid;
        float wc = weight[g * CPG + c];
        float acc = 0.f;
#pragma unroll
        for (int d = 0; d < CPG; d++) acc += T1[c][d] * meanmix[d];
        g_b0[ng][c] = bias[g * CPG + c] - wc * acc;
    }
    cudaTriggerProgrammaticLaunchCompletion();
}

// ------------------------------------------------------------------
// Kernel 3: apply. PDL: prefetch all 16 x float4 loads (independent
// of whiten) before waiting, then read g_A/g_b0.
// ------------------------------------------------------------------
__global__ __launch_bounds__(256) void apply_kernel(const float* __restrict__ x,
                                                    float* __restrict__ out) {
    int b = blockIdx.x;
    int ng = b >> 2;                 // / K3_SPLIT
    int chunk = b & (K3_SPLIT - 1);
    int n = ng >> 4;
    int g = ng & 15;
    int tid = threadIdx.x;

    size_t base = (size_t)(n * C_TOT + g * CPG) * HW
                + (size_t)chunk * K3_POS + (size_t)tid * 4;

    // prework: x loads do not depend on whiten
    float4 v[CPG];
#pragma unroll
    for (int d = 0; d < CPG; d++)
        v[d] = *(const float4*)(x + base + (size_t)d * HW);

    cudaGridDependencySynchronize();      // wait for whiten grid

    __shared__ float sA[CPG][CPG];
    __shared__ float sb[CPG];
    sA[tid >> 4][tid & 15] = g_A[ng][tid];
    if (tid < CPG) sb[tid] = g_b0[ng][tid];
    __syncthreads();

#pragma unroll
    for (int c = 0; c < CPG; c++) {
        float bc = sb[c];
        float4 acc = make_float4(bc, bc, bc, bc);
#pragma unroll
        for (int d = 0; d < CPG; d++) {
            float a = sA[c][d];
            acc.x += a * v[d].x;
            acc.y += a * v[d].y;
            acc.z += a * v[d].z;
            acc.w += a * v[d].w;
        }
        *(float4*)(out + base + (size_t)c * HW) = acc;
    }
}

// ------------------------------------------------------------------
extern "C" void kernel_launch(void* const* d_in, const int* in_sizes, int n_in,
                              void* d_out, int out_size) {
    const float* x      = (const float*)d_in[0];
    const float* sw_m   = (const float*)d_in[1];
    const float* sw_v   = (const float*)d_in[2];
    const float* weight = (const float*)d_in[3];
    const float* bias   = (const float*)d_in[4];
    float* out = (float*)d_out;

    stats_kernel<<<NG, 256>>>(x);
    bw_kernel<<<GROUPS, 256>>>();

    cudaLaunchAttribute attr[1];
    attr[0].id = cudaLaunchAttributeProgrammaticStreamSerialization;
    attr[0].val.programmaticStreamSerializationAllowed = 1;

    {   // whiten with PDL on bw
        cudaLaunchConfig_t cfg = {};
        cfg.gridDim = dim3(NG, 1, 1);
        cfg.blockDim = dim3(256, 1, 1);
        cfg.dynamicSmemBytes = 0;
        cfg.stream = 0;
        cfg.attrs = attr;
        cfg.numAttrs = 1;
        cudaLaunchKernelEx(&cfg, whiten_kernel, sw_m, sw_v, weight, bias);
    }
    {   // apply with PDL on whiten
        cudaLaunchConfig_t cfg = {};
        cfg.gridDim = dim3(NG * K3_SPLIT, 1, 1);
        cfg.blockDim = dim3(256, 1, 1);
        cfg.dynamicSmemBytes = 0;
        cfg.stream = 0;
        cfg.attrs = attr;
        cfg.numAttrs = 1;
        cudaLaunchKernelEx(&cfg, apply_kernel, x, out);
    }
}